// round 2
// baseline (speedup 1.0000x reference)
#include <cuda_runtime.h>
#include <cstdint>

// Problem constants
#define INC   64
#define DDIM  24
#define BATCH 16
#define DSP   (DDIM*DDIM*DDIM)      // 13824 spatial positions per (b,c)
#define NPOS  (BATCH*DSP)           // 221184
#define ODIM  47
#define OSP   (ODIM*ODIM*ODIM)      // 103823

// Scratch: B[b][k][z][y][x], k in [0,27)  (~23.9 MB, static device global)
__device__ float g_B[(size_t)BATCH * 27 * DSP];

// ---- packed f32x2 helpers (sm_103a) ----
__device__ __forceinline__ unsigned long long pack2(float lo, float hi) {
    unsigned long long r;
    asm("mov.b64 %0, {%1, %2};" : "=l"(r) : "f"(lo), "f"(hi));
    return r;
}
__device__ __forceinline__ void unpack2(unsigned long long v, float& lo, float& hi) {
    asm("mov.b64 {%0, %1}, %2;" : "=f"(lo), "=f"(hi) : "l"(v));
}
__device__ __forceinline__ unsigned long long fma2(unsigned long long a,
                                                   unsigned long long b,
                                                   unsigned long long c) {
    unsigned long long d;
    asm("fma.rn.f32x2 %0, %1, %2, %3;" : "=l"(d) : "l"(a), "l"(b), "l"(c));
    return d;
}

// ============================================================
// Pass 1: B[pos][k] = sum_c x[b,c,pos] * W[c,0,k]   (k = 0..26)
// One thread per input spatial position. Channel loop with
// packed-pair accumulation over k (14 f32x2 accumulators).
// ============================================================
__global__ void __launch_bounds__(256) conv_pass1(const float* __restrict__ x,
                                                  const float* __restrict__ w) {
    // Weights: sW[c][k], row padded to 28 floats (112B, 16B-aligned rows).
    __shared__ __align__(16) float sW[64 * 28];
    const int tid = threadIdx.x;
    for (int idx = tid; idx < 64 * 27; idx += blockDim.x) {
        int c = idx / 27, k = idx - c * 27;
        // weight layout (IN_C, OUT_C, 3,3,3): W[c][0][k] at c*64*27 + k
        sW[c * 28 + k] = w[c * 1728 + k];
    }
    if (tid < 64) sW[tid * 28 + 27] = 0.0f;   // pad lane for pair 13
    __syncthreads();

    const int p = blockIdx.x * 256 + tid;     // grid sized exactly to NPOS
    const int b  = p / DSP;
    const int sp = p - b * DSP;
    const float* xp = x + (size_t)b * INC * DSP + sp;

    unsigned long long acc[14];
#pragma unroll
    for (int j = 0; j < 14; j++) acc[j] = 0ull;

#pragma unroll 2
    for (int c = 0; c < INC; c++) {
        const float xv = xp[(size_t)c * DSP];
        const unsigned long long x2 = pack2(xv, xv);
        const ulonglong2* wrow = (const ulonglong2*)(&sW[c * 28]);
#pragma unroll
        for (int j = 0; j < 7; j++) {
            ulonglong2 wp = wrow[j];
            acc[2 * j]     = fma2(x2, wp.x, acc[2 * j]);
            acc[2 * j + 1] = fma2(x2, wp.y, acc[2 * j + 1]);
        }
    }

    float* Bp = g_B + (size_t)b * 27 * DSP + sp;
#pragma unroll
    for (int j = 0; j < 14; j++) {
        float lo, hi;
        unpack2(acc[j], lo, hi);
        const int k0 = 2 * j;
        Bp[(size_t)k0 * DSP] = lo;
        if (k0 + 1 < 27) Bp[(size_t)(k0 + 1) * DSP] = hi;
    }
}

// ============================================================
// Pass 2: out[b,od,oh,ow] = ( sum_{kd,kh,kw} B[b][(2-kd)*9+(2-kh)*3+(2-kw)]
//                              [(od+kd-1)>>1, (oh+kh-1)>>1, (ow+kw-1)>>1]
//                            + bias[0] ) * 64
// Only the low edge (index -1) needs masking; high side never overflows.
// ============================================================
__global__ void __launch_bounds__(256) conv_pass2(const float* __restrict__ bias,
                                                  float* __restrict__ out,
                                                  int out_size) {
    const int i = blockIdx.x * 256 + threadIdx.x;
    if (i >= out_size) return;

    int t  = i;
    const int ow = t % ODIM; t /= ODIM;
    const int oh = t % ODIM; t /= ODIM;
    const int od = t % ODIM;
    const int b  = t / ODIM;

    const float* Bb = g_B + (size_t)b * 27 * DSP;

    float s = 0.0f;
#pragma unroll
    for (int kd = 0; kd < 3; kd++) {
        const int zz = od + kd - 1;
        if (zz < 0) continue;
        const int iz = zz >> 1;
#pragma unroll
        for (int kh = 0; kh < 3; kh++) {
            const int yy = oh + kh - 1;
            if (yy < 0) continue;
            const int iy = yy >> 1;
#pragma unroll
            for (int kw = 0; kw < 3; kw++) {
                const int xx = ow + kw - 1;
                if (xx < 0) continue;
                const int ix = xx >> 1;
                const int k = (2 - kd) * 9 + (2 - kh) * 3 + (2 - kw);
                s += Bb[(size_t)k * DSP + iz * (DDIM * DDIM) + iy * DDIM + ix];
            }
        }
    }
    out[i] = (s + bias[0]) * 64.0f;
}

extern "C" void kernel_launch(void* const* d_in, const int* in_sizes, int n_in,
                              void* d_out, int out_size) {
    const float* x    = (const float*)d_in[0];  // (16,64,24,24,24) fp32
    const float* w    = (const float*)d_in[1];  // (64,64,3,3,3)   fp32
    const float* bias = (const float*)d_in[2];  // (64,)           fp32
    float* out = (float*)d_out;                 // (16,1,47,47,47) fp32

    conv_pass1<<<NPOS / 256, 256>>>(x, w);                       // 864 blocks
    conv_pass2<<<(out_size + 255) / 256, 256>>>(bias, out, out_size);
}

// round 3
// speedup vs baseline: 1.4043x; 1.4043x over previous
#include <cuda_runtime.h>
#include <cstdint>

#define INC   64
#define DDIM  24
#define BATCH 16
#define DSP   (DDIM*DDIM*DDIM)      // 13824
#define NPOS  (BATCH*DSP)           // 221184
#define ODIM  47

// Scratch: B[b][k][z][y][x], k in [0,27)  (~23.9 MB)
__device__ float g_B[(size_t)BATCH * 27 * DSP];

// ---- packed f32x2 helpers ----
__device__ __forceinline__ unsigned long long pack2(float lo, float hi) {
    unsigned long long r;
    asm("mov.b64 %0, {%1, %2};" : "=l"(r) : "f"(lo), "f"(hi));
    return r;
}
__device__ __forceinline__ void unpack2(unsigned long long v, float& lo, float& hi) {
    asm("mov.b64 {%0, %1}, %2;" : "=f"(lo), "=f"(hi) : "l"(v));
}
__device__ __forceinline__ unsigned long long fma2(unsigned long long a,
                                                   unsigned long long b,
                                                   unsigned long long c) {
    unsigned long long d;
    asm("fma.rn.f32x2 %0, %1, %2, %3;" : "=l"(d) : "l"(a), "l"(b), "l"(c));
    return d;
}

// ============================================================
// Pass 1: B[pos][k] = sum_c x[b,c,pos] * W[c,0,k]
// 2 spatial positions per thread -> halves weight-LDS per FMA,
// doubles independent FFMA2 chains.
// ============================================================
__global__ void __launch_bounds__(256) conv_pass1(const float* __restrict__ x,
                                                  const float* __restrict__ w) {
    __shared__ __align__(16) float sW[64 * 28];
    const int tid = threadIdx.x;
    for (int idx = tid; idx < 64 * 27; idx += 256) {
        int c = idx / 27, k = idx - c * 27;
        sW[c * 28 + k] = w[c * 1728 + k];   // W[c][0][k]
    }
    if (tid < 64) sW[tid * 28 + 27] = 0.0f;
    __syncthreads();

    const int p0 = blockIdx.x * 512 + tid;   // grid = NPOS/512; 512 | DSP so
    const int b  = p0 / DSP;                 // both positions share the batch
    const int sp = p0 - b * DSP;
    const float* xp = x + (size_t)b * INC * DSP + sp;

    unsigned long long a0[14], a1[14];
#pragma unroll
    for (int j = 0; j < 14; j++) { a0[j] = 0ull; a1[j] = 0ull; }

#pragma unroll 4
    for (int c = 0; c < INC; c++) {
        const float xv0 = xp[(size_t)c * DSP];
        const float xv1 = xp[(size_t)c * DSP + 256];
        const unsigned long long x20 = pack2(xv0, xv0);
        const unsigned long long x21 = pack2(xv1, xv1);
        const ulonglong2* wrow = (const ulonglong2*)(&sW[c * 28]);
#pragma unroll
        for (int j = 0; j < 7; j++) {
            ulonglong2 wp = wrow[j];
            a0[2 * j]     = fma2(x20, wp.x, a0[2 * j]);
            a1[2 * j]     = fma2(x21, wp.x, a1[2 * j]);
            a0[2 * j + 1] = fma2(x20, wp.y, a0[2 * j + 1]);
            a1[2 * j + 1] = fma2(x21, wp.y, a1[2 * j + 1]);
        }
    }

    float* Bp = g_B + (size_t)b * 27 * DSP + sp;
#pragma unroll
    for (int j = 0; j < 14; j++) {
        float l0, h0, l1, h1;
        unpack2(a0[j], l0, h0);
        unpack2(a1[j], l1, h1);
        const int k0 = 2 * j;
        Bp[(size_t)k0 * DSP]       = l0;
        Bp[(size_t)k0 * DSP + 256] = l1;
        if (k0 + 1 < 27) {
            Bp[(size_t)(k0 + 1) * DSP]       = h0;
            Bp[(size_t)(k0 + 1) * DSP + 256] = h1;
        }
    }
}

// ============================================================
// Pass 2: one thread = one 2x2x2 output octet.
// Per dim, the 5 distinct (input position, weight tap) pairs are:
//   idx 0: (q-1, w=2)   even-parity only
//   idx 1: (q  , w=0)   even-parity only
//   idx 2: (q  , w=1)   both parities
//   idx 3: (q  , w=2)   odd-parity only
//   idx 4: (q+1, w=0)   odd-parity only
// even sum uses {0,1,2}, odd sum uses {2,3,4}.
// 125 loads + separable partial sums -> 8 outputs.
// ============================================================
__global__ void __launch_bounds__(256) conv_pass2(const float* __restrict__ bias,
                                                  float* __restrict__ out) {
    int t = blockIdx.x * 256 + threadIdx.x;   // grid = 221184/256 = 864
    const int qx = t % 24; t /= 24;
    const int qy = t % 24; t /= 24;
    const int qz = t % 24;
    const int b  = t / 24;

    const float* __restrict__ Bb = g_B + (size_t)b * 27 * DSP;

    // per-dim pair tables (compile-time wi, runtime pos/valid)
    const int wiT[5]  = {2, 0, 1, 2, 0};
    const int dposT[5] = {-1, 0, 0, 0, 1};

    // z / y / x offsets (element offset into Bb) and validity
    long zoff[5]; bool zv[5];
    long yoff[5]; bool yv[5];
    long xoff[5]; bool xv[5];
#pragma unroll
    for (int i = 0; i < 5; i++) {
        int pz = qz + dposT[i];
        zv[i]  = (pz >= 0) && (pz < DDIM);
        zoff[i] = (long)wiT[i] * 9 * DSP + (long)pz * (DDIM * DDIM);
        int py = qy + dposT[i];
        yv[i]  = (py >= 0) && (py < DDIM);
        yoff[i] = (long)wiT[i] * 3 * DSP + (long)py * DDIM;
        int px = qx + dposT[i];
        xv[i]  = (px >= 0) && (px < DDIM);
        xoff[i] = (long)wiT[i] * DSP + px;
    }

    float o8[2][2][2];
#pragma unroll
    for (int a = 0; a < 2; a++)
#pragma unroll
        for (int c = 0; c < 2; c++)
#pragma unroll
            for (int d = 0; d < 2; d++) o8[a][c][d] = 0.0f;

#pragma unroll
    for (int iz = 0; iz < 5; iz++) {
        float ys[2][2] = {{0.0f, 0.0f}, {0.0f, 0.0f}};   // [py][pw]
#pragma unroll
        for (int iy = 0; iy < 5; iy++) {
            float v[5];
            const bool vzy = zv[iz] && yv[iy];
            const long base = zoff[iz] + yoff[iy];
#pragma unroll
            for (int ix = 0; ix < 5; ix++) {
                v[ix] = (vzy && xv[ix]) ? Bb[base + xoff[ix]] : 0.0f;
            }
            const float xs0 = v[0] + v[1] + v[2];   // even w
            const float xs1 = v[2] + v[3] + v[4];   // odd  w
            if (iy <= 2) { ys[0][0] += xs0; ys[0][1] += xs1; }
            if (iy >= 2) { ys[1][0] += xs0; ys[1][1] += xs1; }
        }
        if (iz <= 2) {
#pragma unroll
            for (int c = 0; c < 2; c++)
#pragma unroll
                for (int d = 0; d < 2; d++) o8[0][c][d] += ys[c][d];
        }
        if (iz >= 2) {
#pragma unroll
            for (int c = 0; c < 2; c++)
#pragma unroll
                for (int d = 0; d < 2; d++) o8[1][c][d] += ys[c][d];
        }
    }

    const float bv = __ldg(bias);
    const int oz0 = 2 * qz, oy0 = 2 * qy, ox0 = 2 * qx;
#pragma unroll
    for (int pz = 0; pz < 2; pz++) {
        if (oz0 + pz >= ODIM) continue;
#pragma unroll
        for (int py = 0; py < 2; py++) {
            if (oy0 + py >= ODIM) continue;
            const long rbase = (((long)b * ODIM + oz0 + pz) * ODIM + oy0 + py) * ODIM;
#pragma unroll
            for (int pw = 0; pw < 2; pw++) {
                if (ox0 + pw >= ODIM) continue;
                out[rbase + ox0 + pw] = (o8[pz][py][pw] + bv) * 64.0f;
            }
        }
    }
}

extern "C" void kernel_launch(void* const* d_in, const int* in_sizes, int n_in,
                              void* d_out, int out_size) {
    const float* x    = (const float*)d_in[0];
    const float* w    = (const float*)d_in[1];
    const float* bias = (const float*)d_in[2];
    float* out = (float*)d_out;

    conv_pass1<<<NPOS / 512, 256>>>(x, w);    // 432 blocks
    conv_pass2<<<NPOS / (256 * 27) * 27 / 1, 256>>>(bias, out);  // 864 blocks (221184 octets)
}